// round 5
// baseline (speedup 1.0000x reference)
#include <cuda_runtime.h>
#include <math.h>
#include <stdint.h>

// Problem constants
#define B_   16
#define T_   243
#define J_   24
#define D_   256
#define H_   8
#define DH_  32
#define BJ_  (B_ * J_)          // 384
#define M_   (BJ_ * T_)         // 93312
#define N_   (3 * D_)           // 768
#define K_   D_                 // 256

// Scratch: q/k/v in [bj][h][t][dh] layout, fp32
__device__ float g_q[BJ_ * H_ * T_ * DH_];
__device__ float g_k[BJ_ * H_ * T_ * DH_];
__device__ float g_v[BJ_ * H_ * T_ * DH_];

// ---------------------------------------------------------------------------
// tf32 helpers
// ---------------------------------------------------------------------------
__device__ __forceinline__ uint32_t f2tf(float f) {
    uint32_t r;
    asm("cvt.rna.tf32.f32 %0, %1;" : "=r"(r) : "f"(f));
    return r;
}

__device__ __forceinline__ void mma_tf32(float c[4], const uint32_t a[4], const uint32_t b[2]) {
    asm volatile(
        "mma.sync.aligned.m16n8k8.row.col.f32.tf32.tf32.f32 "
        "{%0,%1,%2,%3}, {%4,%5,%6,%7}, {%8,%9}, {%0,%1,%2,%3};\n"
        : "+f"(c[0]), "+f"(c[1]), "+f"(c[2]), "+f"(c[3])
        : "r"(a[0]), "r"(a[1]), "r"(a[2]), "r"(a[3]), "r"(b[0]), "r"(b[1]));
}

// ---------------------------------------------------------------------------
// QKV GEMM: qkv[m, n] = sum_k x[m, k] * W[n, k] + bias[n]
//   m = (b*J + j)*T + t ; x row base = ((b*T + t)*J + j)*D (gathered)
//   n = c*256 + h*32 + dd ; scattered into g_q / g_k / g_v
// Block tile 128x128, BK=32, 8 warps, warp tile 32(M) x 64(N), tf32 MMA.
// ---------------------------------------------------------------------------
#define BM 128
#define BN 128
#define BK 32
#define SSTR 36   // smem row stride in elements (pad for conflict-free frags)

__global__ void __launch_bounds__(256)
qkv_gemm_kernel(const float* __restrict__ X,
                const float* __restrict__ Wq,
                const float* __restrict__ bias)
{
    __shared__ uint32_t As[BM][SSTR];
    __shared__ uint32_t Bs[BN][SSTR];

    const int tid  = threadIdx.x;
    const int lane = tid & 31;
    const int warp = tid >> 5;
    const int wm   = warp & 3;   // 0..3 -> M offset wm*32
    const int wn   = warp >> 2;  // 0..1 -> N offset wn*64

    const int m_base = blockIdx.y * BM;
    const int n_base = blockIdx.x * BN;

    // Global load assignments: each thread loads 4 rows x one float4 per tile
    const int lrow = tid >> 3;          // 0..31
    const int lcol = (tid & 7) * 4;     // 0,4,...,28

    const float* a_ptr[4];
    int row_m[4];
    #pragma unroll
    for (int i = 0; i < 4; ++i) {
        int m  = m_base + lrow + i * 32;
        row_m[i] = m;
        int bj = m / T_;
        int t  = m - bj * T_;
        int b  = bj / J_;
        int j  = bj - b * J_;
        a_ptr[i] = X + ((size_t)((b * T_ + t) * J_ + j) * D_);
    }
    (void)row_m;

    const float* b_ptr[4];
    #pragma unroll
    for (int i = 0; i < 4; ++i) {
        int n = n_base + lrow + i * 32;
        b_ptr[i] = Wq + (size_t)n * K_;
    }

    float acc[2][8][4];
    #pragma unroll
    for (int mi = 0; mi < 2; ++mi)
        #pragma unroll
        for (int ni = 0; ni < 8; ++ni)
            #pragma unroll
            for (int r = 0; r < 4; ++r)
                acc[mi][ni][r] = 0.0f;

    const int gi = lane >> 2;   // groupID 0..7
    const int tg = lane & 3;    // threadID in group 0..3

    #pragma unroll 1
    for (int kb = 0; kb < K_ / BK; ++kb) {
        const int koff = kb * BK + lcol;

        float4 av[4], bv[4];
        #pragma unroll
        for (int i = 0; i < 4; ++i) av[i] = *(const float4*)(a_ptr[i] + koff);
        #pragma unroll
        for (int i = 0; i < 4; ++i) bv[i] = *(const float4*)(b_ptr[i] + koff);

        // STS with tf32 round-to-nearest conversion
        #pragma unroll
        for (int i = 0; i < 4; ++i) {
            uint4 u;
            u.x = f2tf(av[i].x); u.y = f2tf(av[i].y);
            u.z = f2tf(av[i].z); u.w = f2tf(av[i].w);
            *(uint4*)&As[lrow + i * 32][lcol] = u;
        }
        #pragma unroll
        for (int i = 0; i < 4; ++i) {
            uint4 u;
            u.x = f2tf(bv[i].x); u.y = f2tf(bv[i].y);
            u.z = f2tf(bv[i].z); u.w = f2tf(bv[i].w);
            *(uint4*)&Bs[lrow + i * 32][lcol] = u;
        }
        __syncthreads();

        #pragma unroll
        for (int ks = 0; ks < 4; ++ks) {
            const int k0 = ks * 8 + tg;

            uint32_t afr[2][4];
            #pragma unroll
            for (int mi = 0; mi < 2; ++mi) {
                int r = wm * 32 + mi * 16 + gi;
                afr[mi][0] = As[r][k0];
                afr[mi][1] = As[r + 8][k0];
                afr[mi][2] = As[r][k0 + 4];
                afr[mi][3] = As[r + 8][k0 + 4];
            }
            uint32_t bfr[8][2];
            #pragma unroll
            for (int ni = 0; ni < 8; ++ni) {
                int c = wn * 64 + ni * 8 + gi;
                bfr[ni][0] = Bs[c][k0];
                bfr[ni][1] = Bs[c][k0 + 4];
            }
            #pragma unroll
            for (int mi = 0; mi < 2; ++mi)
                #pragma unroll
                for (int ni = 0; ni < 8; ++ni)
                    mma_tf32(acc[mi][ni], afr[mi], bfr[ni]);
        }
        __syncthreads();
    }

    // Epilogue: add bias, scatter into g_q/g_k/g_v in [bj][h][t][dh] layout.
    // Thread owns rows: wm*32 + mi*16 + {gi, gi+8}; cols: wn*64 + ni*8 + 2*tg (+1)
    int robase[2][2];
    #pragma unroll
    for (int mi = 0; mi < 2; ++mi) {
        #pragma unroll
        for (int rr = 0; rr < 2; ++rr) {
            int m  = m_base + wm * 32 + mi * 16 + rr * 8 + gi;
            int bj = m / T_;
            int t  = m - bj * T_;
            robase[mi][rr] = bj * (H_ * T_) + t;   // idx = (robase + h*T_)*DH_ + dd
        }
    }

    #pragma unroll
    for (int ni = 0; ni < 8; ++ni) {
        int n = n_base + wn * 64 + ni * 8 + 2 * tg;   // even
        float b0 = bias[n];
        float b1 = bias[n + 1];
        float* dst = (n < 256) ? g_q : (n < 512) ? g_k : g_v;
        int h  = (n >> 5) & 7;
        int dd = n & 31;
        #pragma unroll
        for (int mi = 0; mi < 2; ++mi) {
            #pragma unroll
            for (int rr = 0; rr < 2; ++rr) {
                float2 v;
                v.x = acc[mi][ni][rr * 2 + 0] + b0;
                v.y = acc[mi][ni][rr * 2 + 1] + b1;
                *(float2*)&dst[(size_t)(robase[mi][rr] + h * T_) * DH_ + dd] = v;
            }
        }
    }
}

// ---------------------------------------------------------------------------
// Windowed attention. One CTA per (bj, h). K,V rows cached in smem
// (row stride 36 floats -> conflict-free float4 LDS). Lanes = t, so the
// 32-d dot products are plain per-lane FMAs (no shuffles).
// ---------------------------------------------------------------------------
#define TSTR 36
#define ATT_SMEM (2 * T_ * TSTR * (int)sizeof(float))   // 69984 bytes

__global__ void __launch_bounds__(256)
attn_kernel(const float* __restrict__ tau, float* __restrict__ out)
{
    extern __shared__ float sm[];
    float* Ks = sm;
    float* Vs = sm + T_ * TSTR;

    const int bjh = blockIdx.x;
    const int bj  = bjh >> 3;
    const int h   = bjh & 7;
    const int b   = bj / J_;
    const int j   = bj - b * J_;
    const size_t base = (size_t)bjh * (T_ * DH_);

    // Stage K, V rows into smem (coalesced float4)
    const float4* kg = (const float4*)(g_k + base);
    const float4* vg = (const float4*)(g_v + base);
    for (int i4 = threadIdx.x; i4 < T_ * DH_ / 4; i4 += 256) {
        int t  = i4 >> 3;
        int d4 = (i4 & 7) << 2;
        float4 kv = kg[i4];
        float4 vv = vg[i4];
        *(float4*)&Ks[t * TSTR + d4] = kv;
        *(float4*)&Vs[t * TSTR + d4] = vv;
    }
    __syncthreads();

    const float scale = 1.0f / (sqrtf(32.0f) * fmaxf(tau[h], 1e-3f));

    const int warp = threadIdx.x >> 5;
    const int lane = threadIdx.x & 31;
    const int t    = warp * 32 + lane;
    const bool tv  = (t < T_);
    const int  tc  = tv ? t : (T_ - 1);

    int  tox[9];
    bool ov[9];
    #pragma unroll
    for (int o = 0; o < 9; ++o) {
        int to = tc + o - 4;
        ov[o]  = (to >= 0) && (to < T_);
        tox[o] = min(max(to, 0), T_ - 1);
    }

    const float* qrow = g_q + base + (size_t)tc * DH_;
    float logit[9];
    #pragma unroll
    for (int o = 0; o < 9; ++o) logit[o] = 0.0f;

    #pragma unroll
    for (int d4 = 0; d4 < DH_; d4 += 4) {
        float4 qd = *(const float4*)(qrow + d4);
        #pragma unroll
        for (int o = 0; o < 9; ++o) {
            float4 kd = *(const float4*)&Ks[tox[o] * TSTR + d4];
            logit[o] += qd.x * kd.x + qd.y * kd.y + qd.z * kd.z + qd.w * kd.w;
        }
    }

    float mx = -1e30f;
    #pragma unroll
    for (int o = 0; o < 9; ++o) {
        logit[o] = ov[o] ? logit[o] * scale : -1e30f;
        mx = fmaxf(mx, logit[o]);
    }
    float w[9];
    float s = 0.0f;
    #pragma unroll
    for (int o = 0; o < 9; ++o) {
        w[o] = ov[o] ? __expf(logit[o] - mx) : 0.0f;
        s += w[o];
    }
    const float inv = 1.0f / s;
    #pragma unroll
    for (int o = 0; o < 9; ++o) w[o] *= inv;

    // out[b, t, j, h*32 + d]
    float* orow = out + ((size_t)((b * T_ + tc) * J_ + j) * D_) + h * DH_;
    #pragma unroll
    for (int d4 = 0; d4 < DH_; d4 += 4) {
        float4 a = make_float4(0.f, 0.f, 0.f, 0.f);
        #pragma unroll
        for (int o = 0; o < 9; ++o) {
            float4 vd = *(const float4*)&Vs[tox[o] * TSTR + d4];
            a.x += w[o] * vd.x;
            a.y += w[o] * vd.y;
            a.z += w[o] * vd.z;
            a.w += w[o] * vd.w;
        }
        if (tv) *(float4*)(orow + d4) = a;
    }
}

// ---------------------------------------------------------------------------
extern "C" void kernel_launch(void* const* d_in, const int* in_sizes, int n_in,
                              void* d_out, int out_size)
{
    (void)in_sizes; (void)n_in; (void)out_size;
    const float* x    = (const float*)d_in[0];  // (B, T, J, D) fp32
    const float* Wq   = (const float*)d_in[1];  // (768, 256)
    const float* bias = (const float*)d_in[2];  // (768,)
    const float* tau  = (const float*)d_in[3];  // (8,)
    float* out = (float*)d_out;

    cudaFuncSetAttribute(attn_kernel,
                         cudaFuncAttributeMaxDynamicSharedMemorySize, ATT_SMEM);

    dim3 ggrid(N_ / BN, M_ / BM);   // (6, 729): n-dim fastest -> A tile L2 reuse
    qkv_gemm_kernel<<<ggrid, 256>>>(x, Wq, bias);
    attn_kernel<<<BJ_ * H_, 256, ATT_SMEM>>>(tau, out);
}

// round 6
// speedup vs baseline: 1.1538x; 1.1538x over previous
#include <cuda_runtime.h>
#include <cuda_bf16.h>
#include <math.h>
#include <stdint.h>

// Problem constants
#define B_   16
#define T_   243
#define J_   24
#define D_   256
#define H_   8
#define DH_  32
#define BJ_  (B_ * J_)          // 384
#define M_   (BJ_ * T_)         // 93312
#define N_   (3 * D_)           // 768
#define K_   D_                 // 256

// Scratch: q/k in bf16, v in fp32, all in [bj*H + h][t][dh] layout
__device__ __nv_bfloat16 g_qb[BJ_ * H_ * T_ * DH_];
__device__ __nv_bfloat16 g_kb[BJ_ * H_ * T_ * DH_];
__device__ float         g_v [BJ_ * H_ * T_ * DH_];

// ---------------------------------------------------------------------------
// tf32 helpers
// ---------------------------------------------------------------------------
__device__ __forceinline__ uint32_t f2tf(float f) {
    uint32_t r;
    asm("cvt.rna.tf32.f32 %0, %1;" : "=r"(r) : "f"(f));
    return r;
}

__device__ __forceinline__ void mma_tf32(float c[4], const uint32_t a[4], const uint32_t b[2]) {
    asm volatile(
        "mma.sync.aligned.m16n8k8.row.col.f32.tf32.tf32.f32 "
        "{%0,%1,%2,%3}, {%4,%5,%6,%7}, {%8,%9}, {%0,%1,%2,%3};\n"
        : "+f"(c[0]), "+f"(c[1]), "+f"(c[2]), "+f"(c[3])
        : "r"(a[0]), "r"(a[1]), "r"(a[2]), "r"(a[3]), "r"(b[0]), "r"(b[1]));
}

// bf16x2 (packed in u32) -> two fp32, exact (shift-based)
__device__ __forceinline__ float2 bup(uint32_t u) {
    float2 r;
    r.x = __uint_as_float(u << 16);
    r.y = __uint_as_float(u & 0xffff0000u);
    return r;
}

// ---------------------------------------------------------------------------
// QKV GEMM: qkv[m, n] = sum_k x[m, k] * W[n, k] + bias[n]
// Block tile 128x128, BK=32, 8 warps, warp tile 32(M) x 64(N), tf32 MMA.
// Double-buffered smem + register prefetch; epilogue bounced through smem
// for coalesced scatter into g_qb/g_kb (bf16) and g_v (fp32).
// ---------------------------------------------------------------------------
#define BM 128
#define BN 128
#define BK 32
#define SSTR 36    // mainloop smem row stride (conflict-free)
#define CSTR 136   // epilogue bounce row stride (conflict-free)

// dynamic smem: A double buf (2*128*36) + B double buf (2*128*36) u32
#define GEMM_SMEM (4 * BM * SSTR * 4)   // 73728 B

__global__ void __launch_bounds__(256)
qkv_gemm_kernel(const float* __restrict__ X,
                const float* __restrict__ Wq,
                const float* __restrict__ bias)
{
    extern __shared__ uint32_t smg[];
    uint32_t* Asm = smg;                    // [2][BM][SSTR]
    uint32_t* Bsm = smg + 2 * BM * SSTR;    // [2][BM][SSTR]
#define AS(s, r, c) Asm[(((s) * BM) + (r)) * SSTR + (c)]
#define BS(s, r, c) Bsm[(((s) * BM) + (r)) * SSTR + (c)]

    const int tid  = threadIdx.x;
    const int lane = tid & 31;
    const int warp = tid >> 5;
    const int wm   = warp & 3;   // M offset wm*32
    const int wn   = warp >> 2;  // N offset wn*64

    const int m_base = blockIdx.y * BM;
    const int n_base = blockIdx.x * BN;

    const int lrow = tid >> 3;          // 0..31
    const int lcol = (tid & 7) * 4;     // 0,4,...,28

    const float* a_ptr[4];
    #pragma unroll
    for (int i = 0; i < 4; ++i) {
        int m  = m_base + lrow + i * 32;
        int bj = m / T_;
        int t  = m - bj * T_;
        int b  = bj / J_;
        int j  = bj - b * J_;
        a_ptr[i] = X + ((size_t)((b * T_ + t) * J_ + j) * D_);
    }
    const float* b_ptr[4];
    #pragma unroll
    for (int i = 0; i < 4; ++i) {
        int n = n_base + lrow + i * 32;
        b_ptr[i] = Wq + (size_t)n * K_;
    }

    float acc[2][8][4];
    #pragma unroll
    for (int mi = 0; mi < 2; ++mi)
        #pragma unroll
        for (int ni = 0; ni < 8; ++ni)
            #pragma unroll
            for (int r = 0; r < 4; ++r)
                acc[mi][ni][r] = 0.0f;

    const int gi = lane >> 2;
    const int tg = lane & 3;

    float4 av[4], bv[4];
    // prologue: load kb=0, STS to buf 0
    #pragma unroll
    for (int i = 0; i < 4; ++i) av[i] = *(const float4*)(a_ptr[i] + lcol);
    #pragma unroll
    for (int i = 0; i < 4; ++i) bv[i] = *(const float4*)(b_ptr[i] + lcol);
    #pragma unroll
    for (int i = 0; i < 4; ++i) {
        uint4 u;
        u.x = f2tf(av[i].x); u.y = f2tf(av[i].y);
        u.z = f2tf(av[i].z); u.w = f2tf(av[i].w);
        *(uint4*)&AS(0, lrow + i * 32, lcol) = u;
    }
    #pragma unroll
    for (int i = 0; i < 4; ++i) {
        uint4 u;
        u.x = f2tf(bv[i].x); u.y = f2tf(bv[i].y);
        u.z = f2tf(bv[i].z); u.w = f2tf(bv[i].w);
        *(uint4*)&BS(0, lrow + i * 32, lcol) = u;
    }
    __syncthreads();

    #pragma unroll 1
    for (int kb = 0; kb < K_ / BK; ++kb) {
        const int cur = kb & 1;

        if (kb < K_ / BK - 1) {
            const int koff = (kb + 1) * BK + lcol;
            #pragma unroll
            for (int i = 0; i < 4; ++i) av[i] = *(const float4*)(a_ptr[i] + koff);
            #pragma unroll
            for (int i = 0; i < 4; ++i) bv[i] = *(const float4*)(b_ptr[i] + koff);
        }

        #pragma unroll
        for (int ks = 0; ks < 4; ++ks) {
            const int k0 = ks * 8 + tg;
            uint32_t afr[2][4];
            #pragma unroll
            for (int mi = 0; mi < 2; ++mi) {
                int r = wm * 32 + mi * 16 + gi;
                afr[mi][0] = AS(cur, r, k0);
                afr[mi][1] = AS(cur, r + 8, k0);
                afr[mi][2] = AS(cur, r, k0 + 4);
                afr[mi][3] = AS(cur, r + 8, k0 + 4);
            }
            uint32_t bfr[8][2];
            #pragma unroll
            for (int ni = 0; ni < 8; ++ni) {
                int c = wn * 64 + ni * 8 + gi;
                bfr[ni][0] = BS(cur, c, k0);
                bfr[ni][1] = BS(cur, c, k0 + 4);
            }
            #pragma unroll
            for (int mi = 0; mi < 2; ++mi)
                #pragma unroll
                for (int ni = 0; ni < 8; ++ni)
                    mma_tf32(acc[mi][ni], afr[mi], bfr[ni]);
        }

        if (kb < K_ / BK - 1) {
            #pragma unroll
            for (int i = 0; i < 4; ++i) {
                uint4 u;
                u.x = f2tf(av[i].x); u.y = f2tf(av[i].y);
                u.z = f2tf(av[i].z); u.w = f2tf(av[i].w);
                *(uint4*)&AS(cur ^ 1, lrow + i * 32, lcol) = u;
            }
            #pragma unroll
            for (int i = 0; i < 4; ++i) {
                uint4 u;
                u.x = f2tf(bv[i].x); u.y = f2tf(bv[i].y);
                u.z = f2tf(bv[i].z); u.w = f2tf(bv[i].w);
                *(uint4*)&BS(cur ^ 1, lrow + i * 32, lcol) = u;
            }
        }
        __syncthreads();
    }

    // ---- Epilogue: bounce through smem for coalesced output ----
    float* Cs = (float*)smg;   // [BM][CSTR], 128*136*4 = 69632 B <= 73728

    #pragma unroll
    for (int ni = 0; ni < 8; ++ni) {
        int nn = wn * 64 + ni * 8 + 2 * tg;
        float b0 = bias[n_base + nn];
        float b1 = bias[n_base + nn + 1];
        #pragma unroll
        for (int mi = 0; mi < 2; ++mi) {
            #pragma unroll
            for (int rr = 0; rr < 2; ++rr) {
                int mm = wm * 32 + mi * 16 + rr * 8 + gi;
                float2 v;
                v.x = acc[mi][ni][rr * 2 + 0] + b0;
                v.y = acc[mi][ni][rr * 2 + 1] + b1;
                *(float2*)&Cs[mm * CSTR + nn] = v;
            }
        }
    }
    __syncthreads();

    const int sel = n_base >> 8;        // 0=q, 1=k, 2=v (BN=128 block inside one matrix)
    #pragma unroll 1
    for (int pass = 0; pass < 16; ++pass) {
        int mm  = pass * 8 + (tid >> 5);
        int nn4 = (tid & 31) * 4;
        int m   = m_base + mm;
        int bj  = m / T_;
        int t   = m - bj * T_;
        int n   = n_base + nn4;
        int h   = (n >> 5) & 7;
        int dd  = n & 31;
        size_t idx = (size_t)((bj * H_ + h) * T_ + t) * DH_ + dd;
        float4 val = *(const float4*)&Cs[mm * CSTR + nn4];
        if (sel == 2) {
            *(float4*)&g_v[idx] = val;
        } else {
            __nv_bfloat162 p0 = __float22bfloat162_rn(make_float2(val.x, val.y));
            __nv_bfloat162 p1 = __float22bfloat162_rn(make_float2(val.z, val.w));
            uint2 u;
            u.x = *(uint32_t*)&p0;
            u.y = *(uint32_t*)&p1;
            __nv_bfloat16* dst = sel ? g_kb : g_qb;
            *(uint2*)&dst[idx] = u;
        }
    }
#undef AS
#undef BS
}

// ---------------------------------------------------------------------------
// Windowed attention. One CTA per (bj, h).
// Q, K staged in smem as bf16 (raw copy from bf16 scratch), V fp32.
// Output bounced through smem (overlaying Q/K region) for coalesced STG.
// ---------------------------------------------------------------------------
#define TSTR 36
// smem: Qs bf16 (243*36) + Ks bf16 (243*36) + Vs f32 (243*36)
#define ATT_SMEM (T_ * TSTR * 2 + T_ * TSTR * 2 + T_ * TSTR * 4)  // 69984 B

__global__ void __launch_bounds__(256, 3)
attn_kernel(const float* __restrict__ tau, float* __restrict__ out)
{
    extern __shared__ char sma[];
    __nv_bfloat16* Qs = (__nv_bfloat16*)sma;            // 8748 elems
    __nv_bfloat16* Ks = Qs + T_ * TSTR;                 // 8748 elems
    float*         Vs = (float*)(sma + 4 * T_ * TSTR);  // 8748 floats
    float*         Os = (float*)sma;                    // overlays Qs+Ks (same 34992 B)

    const int bjh = blockIdx.x;
    const int bj  = bjh >> 3;
    const int h   = bjh & 7;
    const int b   = bj / J_;
    const int j   = bj - b * J_;
    const size_t base = (size_t)bjh * (T_ * DH_);

    // Stage Q, K (bf16 raw), V (fp32) -- all coalesced
    {
        const uint2*  qg = (const uint2*)(g_qb + base);
        const uint2*  kg = (const uint2*)(g_kb + base);
        const float4* vg = (const float4*)(g_v + base);
        for (int i4 = threadIdx.x; i4 < T_ * DH_ / 4; i4 += 256) {
            int t  = i4 >> 3;
            int d4 = (i4 & 7) << 2;
            uint2  qv = qg[i4];
            uint2  kv = kg[i4];
            float4 vv = vg[i4];
            *(uint2*)&Qs[t * TSTR + d4]  = qv;
            *(uint2*)&Ks[t * TSTR + d4]  = kv;
            *(float4*)&Vs[t * TSTR + d4] = vv;
        }
    }
    __syncthreads();

    const float scale = 1.0f / (sqrtf(32.0f) * fmaxf(tau[h], 1e-3f));

    const int t  = threadIdx.x;
    const bool tv = (t < T_);
    const int  tc = tv ? t : (T_ - 1);

    int  tox[9];
    bool ov[9];
    #pragma unroll
    for (int o = 0; o < 9; ++o) {
        int to = tc + o - 4;
        ov[o]  = (to >= 0) && (to < T_);
        tox[o] = min(max(to, 0), T_ - 1);
    }

    float logit[9];
    #pragma unroll
    for (int o = 0; o < 9; ++o) logit[o] = 0.0f;

    #pragma unroll
    for (int d4 = 0; d4 < DH_; d4 += 4) {
        uint2 qu = *(const uint2*)&Qs[tc * TSTR + d4];
        float2 qa = bup(qu.x);
        float2 qb = bup(qu.y);
        #pragma unroll
        for (int o = 0; o < 9; ++o) {
            uint2 ku = *(const uint2*)&Ks[tox[o] * TSTR + d4];
            float2 ka = bup(ku.x);
            float2 kb = bup(ku.y);
            logit[o] += qa.x * ka.x + qa.y * ka.y + qb.x * kb.x + qb.y * kb.y;
        }
    }

    float mx = -1e30f;
    #pragma unroll
    for (int o = 0; o < 9; ++o) {
        logit[o] = ov[o] ? logit[o] * scale : -1e30f;
        mx = fmaxf(mx, logit[o]);
    }
    float w[9];
    float s = 0.0f;
    #pragma unroll
    for (int o = 0; o < 9; ++o) {
        w[o] = ov[o] ? __expf(logit[o] - mx) : 0.0f;
        s += w[o];
    }
    const float inv = 1.0f / s;
    #pragma unroll
    for (int o = 0; o < 9; ++o) w[o] *= inv;

    // All Q/K smem reads done across the CTA before overlaying with Os
    __syncthreads();

    #pragma unroll
    for (int d4 = 0; d4 < DH_; d4 += 4) {
        float4 a = make_float4(0.f, 0.f, 0.f, 0.f);
        #pragma unroll
        for (int o = 0; o < 9; ++o) {
            float4 vd = *(const float4*)&Vs[tox[o] * TSTR + d4];
            a.x += w[o] * vd.x;
            a.y += w[o] * vd.y;
            a.z += w[o] * vd.z;
            a.w += w[o] * vd.w;
        }
        if (tv) *(float4*)&Os[tc * TSTR + d4] = a;
    }
    __syncthreads();

    // Coalesced output: out[b, t, j, h*32 + d]
    for (int i4 = threadIdx.x; i4 < T_ * DH_ / 4; i4 += 256) {
        int tt = i4 >> 3;
        int d4 = (i4 & 7) << 2;
        float4 a = *(const float4*)&Os[tt * TSTR + d4];
        float* orow = out + ((size_t)((b * T_ + tt) * J_ + j) * D_) + h * DH_;
        *(float4*)(orow + d4) = a;
    }
}

// ---------------------------------------------------------------------------
extern "C" void kernel_launch(void* const* d_in, const int* in_sizes, int n_in,
                              void* d_out, int out_size)
{
    (void)in_sizes; (void)n_in; (void)out_size;
    const float* x    = (const float*)d_in[0];  // (B, T, J, D) fp32
    const float* Wq   = (const float*)d_in[1];  // (768, 256)
    const float* bias = (const float*)d_in[2];  // (768,)
    const float* tau  = (const float*)d_in[3];  // (8,)
    float* out = (float*)d_out;

    cudaFuncSetAttribute(qkv_gemm_kernel,
                         cudaFuncAttributeMaxDynamicSharedMemorySize, GEMM_SMEM);
    cudaFuncSetAttribute(attn_kernel,
                         cudaFuncAttributeMaxDynamicSharedMemorySize, ATT_SMEM);

    dim3 ggrid(N_ / BN, M_ / BM);   // (6, 729): n-dim fastest -> X tile L2 reuse
    qkv_gemm_kernel<<<ggrid, 256, GEMM_SMEM>>>(x, Wq, bias);
    attn_kernel<<<BJ_ * H_, 256, ATT_SMEM>>>(tau, out);
}

// round 8
// speedup vs baseline: 1.4827x; 1.2850x over previous
#include <cuda_runtime.h>
#include <cuda_fp16.h>
#include <math.h>
#include <stdint.h>

// Problem constants
#define B_   16
#define T_   243
#define J_   24
#define D_   256
#define H_   8
#define DH_  32
#define BJ_  (B_ * J_)          // 384
#define M_   (BJ_ * T_)         // 93312
#define N_   (3 * D_)           // 768
#define K_   D_                 // 256

// Scratch: q/k/v all fp16, [bj*H + h][t][dh] layout
__device__ __half g_q[BJ_ * H_ * T_ * DH_];
__device__ __half g_k[BJ_ * H_ * T_ * DH_];
__device__ __half g_v[BJ_ * H_ * T_ * DH_];

// ---------------------------------------------------------------------------
// helpers
// ---------------------------------------------------------------------------
__device__ __forceinline__ uint32_t smem_u32(const void* p) {
    uint32_t a;
    asm("{ .reg .u64 t; cvta.to.shared.u64 t, %1; cvt.u32.u64 %0, t; }" : "=r"(a) : "l"(p));
    return a;
}

__device__ __forceinline__ void ldsm_x4(uint32_t r[4], uint32_t addr) {
    asm volatile("ldmatrix.sync.aligned.m8n8.x4.shared.b16 {%0,%1,%2,%3}, [%4];"
                 : "=r"(r[0]), "=r"(r[1]), "=r"(r[2]), "=r"(r[3]) : "r"(addr));
}

__device__ __forceinline__ void mma_f16(float c[4], const uint32_t a[4],
                                        uint32_t b0, uint32_t b1) {
    asm volatile(
        "mma.sync.aligned.m16n8k16.row.col.f32.f16.f16.f32 "
        "{%0,%1,%2,%3}, {%4,%5,%6,%7}, {%8,%9}, {%0,%1,%2,%3};\n"
        : "+f"(c[0]), "+f"(c[1]), "+f"(c[2]), "+f"(c[3])
        : "r"(a[0]), "r"(a[1]), "r"(a[2]), "r"(a[3]), "r"(b0), "r"(b1));
}

__device__ __forceinline__ uint4 pack8h(float4 a, float4 b) {
    uint4 u;
    __half2 h;
    h = __floats2half2_rn(a.x, a.y); u.x = *(uint32_t*)&h;
    h = __floats2half2_rn(a.z, a.w); u.y = *(uint32_t*)&h;
    h = __floats2half2_rn(b.x, b.y); u.z = *(uint32_t*)&h;
    h = __floats2half2_rn(b.z, b.w); u.w = *(uint32_t*)&h;
    return u;
}

__device__ __forceinline__ float2 h2f(uint32_t u) {
    __half2 h = *reinterpret_cast<__half2*>(&u);
    return __half22float2(h);
}

// ---------------------------------------------------------------------------
// QKV GEMM: qkv[m,n] = sum_k X[m,k] * W[n,k] + bias[n], fp16 mma m16n8k16.
// Tile 128x128, K slabs of 64 fp16 (128B rows, SW128), double-buffered.
// 8 warps, warp tile 32(M) x 64(N). ldmatrix fragment loads.
// Epilogue bounced through smem, coalesced fp16 scatter into g_q/g_k/g_v.
// ---------------------------------------------------------------------------
#define BM 128
#define BN 128
#define STAGE_SZ 32768   // A 16KB + B 16KB
#define CSTR2 132
#define GOFF_BIAS (BM * CSTR2 * 4)              // 67584
#define GEMM_SMEM (GOFF_BIAS + 512)             // 68096

__global__ void __launch_bounds__(256)
qkv_gemm(const float* __restrict__ X,
         const float* __restrict__ Wq,
         const float* __restrict__ bias)
{
    extern __shared__ char smem[];
    const uint32_t sb = smem_u32(smem);
    float* sBias = (float*)(smem + GOFF_BIAS);

    const int tid  = threadIdx.x;
    const int lane = tid & 31;
    const int warp = tid >> 5;
    const int wm   = warp & 3;    // M offset wm*32
    const int wn   = warp >> 2;   // N offset wn*64
    const int m_base = blockIdx.y * BM;
    const int n_base = blockIdx.x * BN;

    if (tid < 128) sBias[tid] = bias[n_base + tid];

    // ---- loader mapping: each thread fills 4 rows x 16B per slab ----
    const int lrow = tid >> 3;        // 0..31
    const int lk   = (tid & 7) * 8;   // fp32 element offset (0..56)
    const float* aR[4];
    const float* bR[4];
    uint32_t so[4];
    #pragma unroll
    for (int jj = 0; jj < 4; ++jj) {
        int row = lrow + jj * 32;
        int m  = m_base + row;
        int bj = m / T_;
        int t  = m - bj * T_;
        int b  = bj / J_;
        int j  = bj - b * J_;
        aR[jj] = X + (size_t)((b * T_ + t) * J_ + j) * D_ + lk;
        bR[jj] = Wq + (size_t)(n_base + row) * K_ + lk;
        so[jj] = row * 128 + 16 * ((tid & 7) ^ (row & 7));   // SW128
    }

    // ---- fragment lane constants (ldmatrix addressing) ----
    const int jrow = lane & 7;
    const int nlo  = (lane >> 3) & 1;   // tile&1: row-half
    const int hi   = lane >> 4;         // tile>>1: k-half
    uint32_t abase[2], ar7[2];
    #pragma unroll
    for (int mi = 0; mi < 2; ++mi) {
        int r = wm * 32 + mi * 16 + nlo * 8 + jrow;
        abase[mi] = r * 128;
        ar7[mi] = r & 7;
    }
    uint32_t bbase[4], br7[4];
    #pragma unroll
    for (int p = 0; p < 4; ++p) {
        int r = wn * 64 + p * 16 + nlo * 8 + jrow;
        bbase[p] = 16384 + r * 128;
        br7[p] = r & 7;
    }

    float acc[2][8][4];
    #pragma unroll
    for (int mi = 0; mi < 2; ++mi)
        #pragma unroll
        for (int ni = 0; ni < 8; ++ni)
            #pragma unroll
            for (int r = 0; r < 4; ++r)
                acc[mi][ni][r] = 0.0f;

    // ---- prologue: load slab 0, STS to stage 0 ----
    uint4 ua[4], ub[4];
    #pragma unroll
    for (int jj = 0; jj < 4; ++jj) {
        float4 a0 = *(const float4*)(aR[jj]);
        float4 a1 = *(const float4*)(aR[jj] + 4);
        float4 b0 = *(const float4*)(bR[jj]);
        float4 b1 = *(const float4*)(bR[jj] + 4);
        ua[jj] = pack8h(a0, a1);
        ub[jj] = pack8h(b0, b1);
    }
    #pragma unroll
    for (int jj = 0; jj < 4; ++jj) {
        *(uint4*)(smem + so[jj])         = ua[jj];
        *(uint4*)(smem + 16384 + so[jj]) = ub[jj];
    }
    __syncthreads();

    #pragma unroll 1
    for (int kb = 0; kb < 4; ++kb) {
        const int cur = kb & 1;
        const uint32_t stg = sb + cur * STAGE_SZ;

        if (kb < 3) {
            const int off = (kb + 1) * 64;
            #pragma unroll
            for (int jj = 0; jj < 4; ++jj) {
                float4 a0 = *(const float4*)(aR[jj] + off);
                float4 a1 = *(const float4*)(aR[jj] + off + 4);
                float4 b0 = *(const float4*)(bR[jj] + off);
                float4 b1 = *(const float4*)(bR[jj] + off + 4);
                ua[jj] = pack8h(a0, a1);
                ub[jj] = pack8h(b0, b1);
            }
        }

        #pragma unroll
        for (int ks = 0; ks < 4; ++ks) {
            const uint32_t cp = 2 * ks + hi;
            uint32_t bfr[4][4];
            #pragma unroll
            for (int p = 0; p < 4; ++p)
                ldsm_x4(bfr[p], stg + bbase[p] + ((cp ^ br7[p]) << 4));
            #pragma unroll
            for (int mi = 0; mi < 2; ++mi) {
                uint32_t afr[4];
                ldsm_x4(afr, stg + abase[mi] + ((cp ^ ar7[mi]) << 4));
                #pragma unroll
                for (int p = 0; p < 4; ++p) {
                    mma_f16(acc[mi][2 * p + 0], afr, bfr[p][0], bfr[p][2]);
                    mma_f16(acc[mi][2 * p + 1], afr, bfr[p][1], bfr[p][3]);
                }
            }
        }

        if (kb < 3) {
            char* nst = smem + (cur ^ 1) * STAGE_SZ;
            #pragma unroll
            for (int jj = 0; jj < 4; ++jj) {
                *(uint4*)(nst + so[jj])         = ua[jj];
                *(uint4*)(nst + 16384 + so[jj]) = ub[jj];
            }
        }
        __syncthreads();
    }

    // ---- epilogue: bounce through smem, coalesced fp16 scatter ----
    float* Cs = (float*)smem;   // [BM][CSTR2]
    const int gi = lane >> 2;
    const int tg = lane & 3;
    #pragma unroll
    for (int ni = 0; ni < 8; ++ni) {
        int nn = wn * 64 + ni * 8 + 2 * tg;
        float b0 = sBias[nn];
        float b1 = sBias[nn + 1];
        #pragma unroll
        for (int mi = 0; mi < 2; ++mi) {
            #pragma unroll
            for (int rr = 0; rr < 2; ++rr) {
                int mm = wm * 32 + mi * 16 + rr * 8 + gi;
                float2 v;
                v.x = acc[mi][ni][rr * 2 + 0] + b0;
                v.y = acc[mi][ni][rr * 2 + 1] + b1;
                *(float2*)&Cs[mm * CSTR2 + nn] = v;
            }
        }
    }
    __syncthreads();

    const int sel = n_base >> 8;   // 0=q, 1=k, 2=v
    __half* dst = (sel == 0) ? g_q : (sel == 1) ? g_k : g_v;
    #pragma unroll 1
    for (int pass = 0; pass < 16; ++pass) {
        int mm  = pass * 8 + (tid >> 5);
        int nn4 = (tid & 31) * 4;
        int m   = m_base + mm;
        int bj  = m / T_;
        int t   = m - bj * T_;
        int n   = n_base + nn4;
        int h   = (n >> 5) & 7;
        int dd  = n & 31;
        size_t idx = (size_t)((bj * H_ + h) * T_ + t) * DH_ + dd;
        float4 val = *(const float4*)&Cs[mm * CSTR2 + nn4];
        __half2 p0 = __floats2half2_rn(val.x, val.y);
        __half2 p1 = __floats2half2_rn(val.z, val.w);
        uint2 u;
        u.x = *(uint32_t*)&p0;
        u.y = *(uint32_t*)&p1;
        *(uint2*)&dst[idx] = u;
    }
}

// ---------------------------------------------------------------------------
// Windowed attention. One CTA per (bj, h). Q/K/V fp16 in smem (stride 36
// halves = 72B rows: uint2 loads conflict-free). Output overlays Q+K region.
// ---------------------------------------------------------------------------
#define TSTR 36
#define ATT_SMEM (3 * T_ * TSTR * 2)   // 52488 B

__global__ void __launch_bounds__(256, 4)
attn_kernel(const float* __restrict__ tau, float* __restrict__ out)
{
    extern __shared__ char sma[];
    __half* Qs = (__half*)sma;
    __half* Ks = Qs + T_ * TSTR;
    __half* Vs = Ks + T_ * TSTR;
    float*  Os = (float*)sma;   // overlays Qs+Ks exactly (34992 B)

    const int bjh = blockIdx.x;
    const int bj  = bjh >> 3;
    const int h   = bjh & 7;
    const int b   = bj / J_;
    const int j   = bj - b * J_;
    const size_t base = (size_t)bjh * (T_ * DH_);

    {
        const uint2* qg = (const uint2*)(g_q + base);
        const uint2* kg = (const uint2*)(g_k + base);
        const uint2* vg = (const uint2*)(g_v + base);
        for (int i4 = threadIdx.x; i4 < T_ * DH_ / 4; i4 += 256) {
            int t  = i4 >> 3;
            int d4 = (i4 & 7) << 2;
            uint2 qv = qg[i4];
            uint2 kv = kg[i4];
            uint2 vv = vg[i4];
            *(uint2*)&Qs[t * TSTR + d4] = qv;
            *(uint2*)&Ks[t * TSTR + d4] = kv;
            *(uint2*)&Vs[t * TSTR + d4] = vv;
        }
    }
    __syncthreads();

    const float scale = 1.0f / (sqrtf(32.0f) * fmaxf(tau[h], 1e-3f));

    const int t  = threadIdx.x;
    const bool tv = (t < T_);
    const int  tc = tv ? t : (T_ - 1);

    int  tox[9];
    bool ov[9];
    #pragma unroll
    for (int o = 0; o < 9; ++o) {
        int to = tc + o - 4;
        ov[o]  = (to >= 0) && (to < T_);
        tox[o] = min(max(to, 0), T_ - 1);
    }

    float logit[9];
    #pragma unroll
    for (int o = 0; o < 9; ++o) logit[o] = 0.0f;

    #pragma unroll
    for (int d4 = 0; d4 < DH_; d4 += 4) {
        uint2 qu = *(const uint2*)&Qs[tc * TSTR + d4];
        float2 q0 = h2f(qu.x), q1 = h2f(qu.y);
        #pragma unroll
        for (int o = 0; o < 9; ++o) {
            uint2 ku = *(const uint2*)&Ks[tox[o] * TSTR + d4];
            float2 k0 = h2f(ku.x), k1 = h2f(ku.y);
            logit[o] += q0.x * k0.x + q0.y * k0.y + q1.x * k1.x + q1.y * k1.y;
        }
    }

    float mx = -1e30f;
    #pragma unroll
    for (int o = 0; o < 9; ++o) {
        logit[o] = ov[o] ? logit[o] * scale : -1e30f;
        mx = fmaxf(mx, logit[o]);
    }
    float w[9];
    float s = 0.0f;
    #pragma unroll
    for (int o = 0; o < 9; ++o) {
        w[o] = ov[o] ? __expf(logit[o] - mx) : 0.0f;
        s += w[o];
    }
    const float inv = 1.0f / s;
    #pragma unroll
    for (int o = 0; o < 9; ++o) w[o] *= inv;

    __syncthreads();   // all Q/K smem reads done before Os overlay

    #pragma unroll
    for (int d4 = 0; d4 < DH_; d4 += 4) {
        float4 a = make_float4(0.f, 0.f, 0.f, 0.f);
        #pragma unroll
        for (int o = 0; o < 9; ++o) {
            uint2 vu = *(const uint2*)&Vs[tox[o] * TSTR + d4];
            float2 v0 = h2f(vu.x), v1 = h2f(vu.y);
            a.x += w[o] * v0.x;
            a.y += w[o] * v0.y;
            a.z += w[o] * v1.x;
            a.w += w[o] * v1.y;
        }
        if (tv) *(float4*)&Os[tc * TSTR + d4] = a;
    }
    __syncthreads();

    for (int i4 = threadIdx.x; i4 < T_ * DH_ / 4; i4 += 256) {
        int tt = i4 >> 3;
        int d4 = (i4 & 7) << 2;
        float4 a = *(const float4*)&Os[tt * TSTR + d4];
        float* orow = out + ((size_t)((b * T_ + tt) * J_ + j) * D_) + h * DH_;
        *(float4*)(orow + d4) = a;
    }
}

// ---------------------------------------------------------------------------
extern "C" void kernel_launch(void* const* d_in, const int* in_sizes, int n_in,
                              void* d_out, int out_size)
{
    (void)in_sizes; (void)n_in; (void)out_size;
    const float* x    = (const float*)d_in[0];
    const float* Wq   = (const float*)d_in[1];
    const float* bias = (const float*)d_in[2];
    const float* tau  = (const float*)d_in[3];
    float* out = (float*)d_out;

    cudaFuncSetAttribute(qkv_gemm,
                         cudaFuncAttributeMaxDynamicSharedMemorySize, GEMM_SMEM);
    cudaFuncSetAttribute(attn_kernel,
                         cudaFuncAttributeMaxDynamicSharedMemorySize, ATT_SMEM);

    dim3 ggrid(N_ / BN, M_ / BM);   // (6, 729): n fastest -> X tile L2 reuse
    qkv_gemm<<<ggrid, 256, GEMM_SMEM>>>(x, Wq, bias);
    attn_kernel<<<BJ_ * H_, 256, ATT_SMEM>>>(tau, out);
}

// round 9
// speedup vs baseline: 1.8597x; 1.2543x over previous
#include <cuda_runtime.h>
#include <cuda_fp16.h>
#include <math.h>
#include <stdint.h>

// Problem constants
#define B_   16
#define T_   243
#define J_   24
#define D_   256
#define H_   8
#define DH_  32
#define BJ_  (B_ * J_)          // 384
#define M_   (BJ_ * T_)         // 93312
#define N_   (3 * D_)           // 768
#define K_   D_                 // 256

// fp16 copies of inputs (X permuted to m-major: row m = (b*J+j)*T + t)
__device__ __half g_xh[(size_t)M_ * K_];
__device__ __half g_wh[(size_t)N_ * K_];
// Scratch: q/k/v fp16, [bj*H + h][t][dh] layout
__device__ __half g_q[BJ_ * H_ * T_ * DH_];
__device__ __half g_k[BJ_ * H_ * T_ * DH_];
__device__ __half g_v[BJ_ * H_ * T_ * DH_];

// ---------------------------------------------------------------------------
// helpers
// ---------------------------------------------------------------------------
__device__ __forceinline__ uint32_t smem_u32(const void* p) {
    uint32_t a;
    asm("{ .reg .u64 t; cvta.to.shared.u64 t, %1; cvt.u32.u64 %0, t; }" : "=r"(a) : "l"(p));
    return a;
}
__device__ __forceinline__ void ldsm_x4(uint32_t r[4], uint32_t addr) {
    asm volatile("ldmatrix.sync.aligned.m8n8.x4.shared.b16 {%0,%1,%2,%3}, [%4];"
                 : "=r"(r[0]), "=r"(r[1]), "=r"(r[2]), "=r"(r[3]) : "r"(addr));
}
__device__ __forceinline__ void mma_f16(float c[4], const uint32_t a[4],
                                        uint32_t b0, uint32_t b1) {
    asm volatile(
        "mma.sync.aligned.m16n8k16.row.col.f32.f16.f16.f32 "
        "{%0,%1,%2,%3}, {%4,%5,%6,%7}, {%8,%9}, {%0,%1,%2,%3};\n"
        : "+f"(c[0]), "+f"(c[1]), "+f"(c[2]), "+f"(c[3])
        : "r"(a[0]), "r"(a[1]), "r"(a[2]), "r"(a[3]), "r"(b0), "r"(b1));
}
__device__ __forceinline__ uint4 pack8h(float4 a, float4 b) {
    uint4 u;
    __half2 h;
    h = __floats2half2_rn(a.x, a.y); u.x = *(uint32_t*)&h;
    h = __floats2half2_rn(a.z, a.w); u.y = *(uint32_t*)&h;
    h = __floats2half2_rn(b.x, b.y); u.z = *(uint32_t*)&h;
    h = __floats2half2_rn(b.z, b.w); u.w = *(uint32_t*)&h;
    return u;
}
__device__ __forceinline__ float2 h2f(uint32_t u) {
    __half2 h = *reinterpret_cast<__half2*>(&u);
    return __half22float2(h);
}

#define CP_ASYNC16(dst, src) \
    asm volatile("cp.async.cg.shared.global [%0], [%1], 16;" :: "r"(dst), "l"(src) : "memory")
#define CP_COMMIT() asm volatile("cp.async.commit_group;" ::: "memory")
#define CP_WAIT(n)  asm volatile("cp.async.wait_group %0;" :: "n"(n) : "memory")

// ---------------------------------------------------------------------------
// Kernel 0: convert X (permute to m-major) and W to fp16.
// One CTA handles 8 rows of 256 fp32 -> fp16. Blocks [0, M/8) do X,
// blocks [M/8, M/8 + N/8) do W.
// ---------------------------------------------------------------------------
#define XROWS_CTA 8
#define CONV_GRID (M_ / XROWS_CTA + N_ / XROWS_CTA)   // 11664 + 96

__global__ void __launch_bounds__(256)
convert_kernel(const float* __restrict__ X, const float* __restrict__ Wq)
{
    const int lane = threadIdx.x & 31;
    const int wrp  = threadIdx.x >> 5;
    const int off  = lane * 8;

    if (blockIdx.x < M_ / XROWS_CTA) {
        int r = blockIdx.x * XROWS_CTA + wrp;          // X row (B,T,J) order
        int b   = r / (T_ * J_);
        int rem = r - b * (T_ * J_);
        int t   = rem / J_;
        int j   = rem - t * J_;
        int m   = (b * J_ + j) * T_ + t;
        const float* src = X + (size_t)r * D_ + off;
        float4 a0 = *(const float4*)(src);
        float4 a1 = *(const float4*)(src + 4);
        *(uint4*)&g_xh[(size_t)m * K_ + off] = pack8h(a0, a1);
    } else {
        int n = (blockIdx.x - M_ / XROWS_CTA) * XROWS_CTA + wrp;
        const float* src = Wq + (size_t)n * K_ + off;
        float4 a0 = *(const float4*)(src);
        float4 a1 = *(const float4*)(src + 4);
        *(uint4*)&g_wh[(size_t)n * K_ + off] = pack8h(a0, a1);
    }
}

// ---------------------------------------------------------------------------
// QKV GEMM: fp16 mma m16n8k16, 128x128 tile, BK=64, 3-stage cp.async pipeline.
// 8 warps, warp tile 32(M) x 64(N), ldmatrix + SW128.
// Epilogue bounced through smem, coalesced fp16 scatter to g_q/g_k/g_v.
// ---------------------------------------------------------------------------
#define BM 128
#define BN 128
#define NSTAGE 3
#define STAGE_SZ 32768   // A 16KB + B 16KB
#define CSTR2 132
#define GOFF_BIAS (NSTAGE * STAGE_SZ)          // 98304
#define GEMM_SMEM (GOFF_BIAS + 512)            // 98816

__global__ void __launch_bounds__(256, 2)
qkv_gemm(const float* __restrict__ bias)
{
    extern __shared__ char smem[];
    const uint32_t sb = smem_u32(smem);
    float* sBias = (float*)(smem + GOFF_BIAS);

    const int tid  = threadIdx.x;
    const int lane = tid & 31;
    const int warp = tid >> 5;
    const int wm   = warp & 3;    // M offset wm*32
    const int wn   = warp >> 2;   // N offset wn*64
    const int m_base = blockIdx.y * BM;
    const int n_base = blockIdx.x * BN;

    if (tid < 128) sBias[tid] = bias[n_base + tid];

    // ---- loader mapping: thread fills 4 A rows + 4 B rows x 16B per stage ----
    const int lrow = tid >> 3;        // 0..31
    const int lk   = (tid & 7) * 8;   // half-elem offset within 64-wide slab
    const __half* aR[4];
    const __half* bR[4];
    uint32_t so[4];
    #pragma unroll
    for (int jj = 0; jj < 4; ++jj) {
        int row = lrow + jj * 32;
        aR[jj] = g_xh + (size_t)(m_base + row) * K_ + lk;
        bR[jj] = g_wh + (size_t)(n_base + row) * K_ + lk;
        so[jj] = row * 128 + 16 * ((tid & 7) ^ (row & 7));   // SW128
    }

    // ---- fragment lane constants (ldmatrix addressing) ----
    const int jrow = lane & 7;
    const int nlo  = (lane >> 3) & 1;
    const int hi   = lane >> 4;
    uint32_t abase[2], ar7[2];
    #pragma unroll
    for (int mi = 0; mi < 2; ++mi) {
        int r = wm * 32 + mi * 16 + nlo * 8 + jrow;
        abase[mi] = r * 128;
        ar7[mi] = r & 7;
    }
    uint32_t bbase[4], br7[4];
    #pragma unroll
    for (int p = 0; p < 4; ++p) {
        int r = wn * 64 + p * 16 + nlo * 8 + jrow;
        bbase[p] = 16384 + r * 128;
        br7[p] = r & 7;
    }

    float acc[2][8][4];
    #pragma unroll
    for (int mi = 0; mi < 2; ++mi)
        #pragma unroll
        for (int ni = 0; ni < 8; ++ni)
            #pragma unroll
            for (int r = 0; r < 4; ++r)
                acc[mi][ni][r] = 0.0f;

    // ---- issue helper (macro to keep addresses in registers) ----
#define ISSUE_STAGE(s, kb) do {                                        \
        uint32_t _b = sb + (s) * STAGE_SZ;                             \
        const int _o = (kb) * 64;                                      \
        CP_ASYNC16(_b + so[0],         (const char*)(aR[0] + _o));     \
        CP_ASYNC16(_b + so[1],         (const char*)(aR[1] + _o));     \
        CP_ASYNC16(_b + so[2],         (const char*)(aR[2] + _o));     \
        CP_ASYNC16(_b + so[3],         (const char*)(aR[3] + _o));     \
        CP_ASYNC16(_b + 16384 + so[0], (const char*)(bR[0] + _o));     \
        CP_ASYNC16(_b + 16384 + so[1], (const char*)(bR[1] + _o));     \
        CP_ASYNC16(_b + 16384 + so[2], (const char*)(bR[2] + _o));     \
        CP_ASYNC16(_b + 16384 + so[3], (const char*)(bR[3] + _o));     \
    } while (0)

    ISSUE_STAGE(0, 0); CP_COMMIT();
    ISSUE_STAGE(1, 1); CP_COMMIT();

    #pragma unroll 1
    for (int kb = 0; kb < 4; ++kb) {
        if (kb == 3) { CP_WAIT(0); } else { CP_WAIT(1); }
        __syncthreads();

        if (kb < 2) { ISSUE_STAGE((kb + 2) % NSTAGE, kb + 2); CP_COMMIT(); }

        const uint32_t stg = sb + (kb % NSTAGE) * STAGE_SZ;
        #pragma unroll
        for (int ks = 0; ks < 4; ++ks) {
            const uint32_t cp = 2 * ks + hi;
            uint32_t bfr[4][4];
            #pragma unroll
            for (int p = 0; p < 4; ++p)
                ldsm_x4(bfr[p], stg + bbase[p] + ((cp ^ br7[p]) << 4));
            #pragma unroll
            for (int mi = 0; mi < 2; ++mi) {
                uint32_t afr[4];
                ldsm_x4(afr, stg + abase[mi] + ((cp ^ ar7[mi]) << 4));
                #pragma unroll
                for (int p = 0; p < 4; ++p) {
                    mma_f16(acc[mi][2 * p + 0], afr, bfr[p][0], bfr[p][2]);
                    mma_f16(acc[mi][2 * p + 1], afr, bfr[p][1], bfr[p][3]);
                }
            }
        }
    }
    __syncthreads();
#undef ISSUE_STAGE

    // ---- epilogue: bounce through smem, coalesced fp16 scatter ----
    float* Cs = (float*)smem;   // [BM][CSTR2] = 67584 B (fits in stage area)
    const int gi = lane >> 2;
    const int tg = lane & 3;
    #pragma unroll
    for (int ni = 0; ni < 8; ++ni) {
        int nn = wn * 64 + ni * 8 + 2 * tg;
        float b0 = sBias[nn];
        float b1 = sBias[nn + 1];
        #pragma unroll
        for (int mi = 0; mi < 2; ++mi) {
            #pragma unroll
            for (int rr = 0; rr < 2; ++rr) {
                int mm = wm * 32 + mi * 16 + rr * 8 + gi;
                float2 v;
                v.x = acc[mi][ni][rr * 2 + 0] + b0;
                v.y = acc[mi][ni][rr * 2 + 1] + b1;
                *(float2*)&Cs[mm * CSTR2 + nn] = v;
            }
        }
    }
    __syncthreads();

    const int sel = n_base >> 8;   // 0=q, 1=k, 2=v
    __half* dst = (sel == 0) ? g_q : (sel == 1) ? g_k : g_v;
    #pragma unroll 1
    for (int pass = 0; pass < 16; ++pass) {
        int mm  = pass * 8 + (tid >> 5);
        int nn4 = (tid & 31) * 4;
        int m   = m_base + mm;
        int bj  = m / T_;
        int t   = m - bj * T_;
        int n   = n_base + nn4;
        int h   = (n >> 5) & 7;
        int dd  = n & 31;
        size_t idx = (size_t)((bj * H_ + h) * T_ + t) * DH_ + dd;
        float4 val = *(const float4*)&Cs[mm * CSTR2 + nn4];
        __half2 p0 = __floats2half2_rn(val.x, val.y);
        __half2 p1 = __floats2half2_rn(val.z, val.w);
        uint2 u;
        u.x = *(uint32_t*)&p0;
        u.y = *(uint32_t*)&p1;
        *(uint2*)&dst[idx] = u;
    }
}

// ---------------------------------------------------------------------------
// Windowed attention (unchanged from R8: 74.8us, matched prediction).
// ---------------------------------------------------------------------------
#define TSTR 36
#define ATT_SMEM (3 * T_ * TSTR * 2)   // 52488 B

__global__ void __launch_bounds__(256, 4)
attn_kernel(const float* __restrict__ tau, float* __restrict__ out)
{
    extern __shared__ char sma[];
    __half* Qs = (__half*)sma;
    __half* Ks = Qs + T_ * TSTR;
    __half* Vs = Ks + T_ * TSTR;
    float*  Os = (float*)sma;   // overlays Qs+Ks exactly (34992 B)

    const int bjh = blockIdx.x;
    const int bj  = bjh >> 3;
    const int h   = bjh & 7;
    const int b   = bj / J_;
    const int j   = bj - b * J_;
    const size_t base = (size_t)bjh * (T_ * DH_);

    {
        const uint2* qg = (const uint2*)(g_q + base);
        const uint2* kg = (const uint2*)(g_k + base);
        const uint2* vg = (const uint2*)(g_v + base);
        for (int i4 = threadIdx.x; i4 < T_ * DH_ / 4; i4 += 256) {
            int t  = i4 >> 3;
            int d4 = (i4 & 7) << 2;
            uint2 qv = qg[i4];
            uint2 kv = kg[i4];
            uint2 vv = vg[i4];
            *(uint2*)&Qs[t * TSTR + d4] = qv;
            *(uint2*)&Ks[t * TSTR + d4] = kv;
            *(uint2*)&Vs[t * TSTR + d4] = vv;
        }
    }
    __syncthreads();

    const float scale = 1.0f / (sqrtf(32.0f) * fmaxf(tau[h], 1e-3f));

    const int t  = threadIdx.x;
    const bool tv = (t < T_);
    const int  tc = tv ? t : (T_ - 1);

    int  tox[9];
    bool ov[9];
    #pragma unroll
    for (int o = 0; o < 9; ++o) {
        int to = tc + o - 4;
        ov[o]  = (to >= 0) && (to < T_);
        tox[o] = min(max(to, 0), T_ - 1);
    }

    float logit[9];
    #pragma unroll
    for (int o = 0; o < 9; ++o) logit[o] = 0.0f;

    #pragma unroll
    for (int d4 = 0; d4 < DH_; d4 += 4) {
        uint2 qu = *(const uint2*)&Qs[tc * TSTR + d4];
        float2 q0 = h2f(qu.x), q1 = h2f(qu.y);
        #pragma unroll
        for (int o = 0; o < 9; ++o) {
            uint2 ku = *(const uint2*)&Ks[tox[o] * TSTR + d4];
            float2 k0 = h2f(ku.x), k1 = h2f(ku.y);
            logit[o] += q0.x * k0.x + q0.y * k0.y + q1.x * k1.x + q1.y * k1.y;
        }
    }

    float mx = -1e30f;
    #pragma unroll
    for (int o = 0; o < 9; ++o) {
        logit[o] = ov[o] ? logit[o] * scale : -1e30f;
        mx = fmaxf(mx, logit[o]);
    }
    float w[9];
    float s = 0.0f;
    #pragma unroll
    for (int o = 0; o < 9; ++o) {
        w[o] = ov[o] ? __expf(logit[o] - mx) : 0.0f;
        s += w[o];
    }
    const float inv = 1.0f / s;
    #pragma unroll
    for (int o = 0; o < 9; ++o) w[o] *= inv;

    __syncthreads();   // all Q/K smem reads done before Os overlay

    #pragma unroll
    for (int d4 = 0; d4 < DH_; d4 += 4) {
        float4 a = make_float4(0.f, 0.f, 0.f, 0.f);
        #pragma unroll
        for (int o = 0; o < 9; ++o) {
            uint2 vu = *(const uint2*)&Vs[tox[o] * TSTR + d4];
            float2 v0 = h2f(vu.x), v1 = h2f(vu.y);
            a.x += w[o] * v0.x;
            a.y += w[o] * v0.y;
            a.z += w[o] * v1.x;
            a.w += w[o] * v1.y;
        }
        if (tv) *(float4*)&Os[tc * TSTR + d4] = a;
    }
    __syncthreads();

    for (int i4 = threadIdx.x; i4 < T_ * DH_ / 4; i4 += 256) {
        int tt = i4 >> 3;
        int d4 = (i4 & 7) << 2;
        float4 a = *(const float4*)&Os[tt * TSTR + d4];
        float* orow = out + ((size_t)((b * T_ + tt) * J_ + j) * D_) + h * DH_;
        *(float4*)(orow + d4) = a;
    }
}

// ---------------------------------------------------------------------------
extern "C" void kernel_launch(void* const* d_in, const int* in_sizes, int n_in,
                              void* d_out, int out_size)
{
    (void)in_sizes; (void)n_in; (void)out_size;
    const float* x    = (const float*)d_in[0];
    const float* Wq   = (const float*)d_in[1];
    const float* bias = (const float*)d_in[2];
    const float* tau  = (const float*)d_in[3];
    float* out = (float*)d_out;

    cudaFuncSetAttribute(qkv_gemm,
                         cudaFuncAttributeMaxDynamicSharedMemorySize, GEMM_SMEM);
    cudaFuncSetAttribute(attn_kernel,
                         cudaFuncAttributeMaxDynamicSharedMemorySize, ATT_SMEM);

    convert_kernel<<<CONV_GRID, 256>>>(x, Wq);
    dim3 ggrid(N_ / BN, M_ / BM);   // (6, 729): n fastest -> X tile L2 reuse
    qkv_gemm<<<ggrid, 256, GEMM_SMEM>>>(bias);
    attn_kernel<<<BJ_ * H_, 256, ATT_SMEM>>>(tau, out);
}